// round 11
// baseline (speedup 1.0000x reference)
#include <cuda_runtime.h>
#include <cstdint>

#define T_STEPS 50
#define BATCH   128
#define NIN     16384
#define NH      256
#define NO      11
#define M_TOT   (T_STEPS * BATCH)    // 6400

#define ROWS    48                   // m-rows per CTA -> 134 CTAs (one wave)
#define NCTA    ((M_TOT + ROWS - 1) / ROWS)   // 134
#define BK      16
#define NCHUNK  (NIN / BK)           // 1024
#define ASW     52                   // As row width in floats (48 + pad)
#define BSW     260                  // Bs row width in floats (256 + pad)

// ---------------------------------------------------------------------------
// Device scratch
// ---------------------------------------------------------------------------
__device__ float g_cur1[(size_t)M_TOT * NH];

// packed dual-fp32 fma: each 32-bit lane is an independent IEEE fp32 RN fma.
// Bitwise-equal per lane to scalar fmaf -> preserves R1's exact arithmetic.
__device__ __forceinline__ void fma_x2(unsigned long long& acc,
                                       unsigned long long a,
                                       unsigned long long b) {
    asm volatile("fma.rn.f32x2 %0, %1, %2, %0;"
                 : "+l"(acc) : "l"(a), "l"(b));
}

__device__ __forceinline__ unsigned long long pack2(float lo, float hi) {
    unsigned long long r;
    asm("mov.b64 %0, {%1, %2};" : "=l"(r) : "f"(lo), "f"(hi));
    return r;
}

__device__ __forceinline__ void unpack2(unsigned long long v,
                                        float& lo, float& hi) {
    asm("mov.b64 {%0, %1}, %2;" : "=f"(lo), "=f"(hi) : "l"(v));
}

// ---------------------------------------------------------------------------
// GEMM: cur1[m][n] = (sum_{k ascending} fma(X[m][k], W1[n][k])) + b1[n]
// Bitwise-identical to the round-1 kernel's arithmetic (one fp32 RN fma per
// k in ascending order per output, single fp32 bias add at the end) --
// the round-1 kernel passed with rel_err == 0.0.
// Tile 48x256, 256 threads (8 warps x 32 lanes), thread tile 6x8,
// acc pairs along adjacent m-rows so packed operands come straight from
// LDS.64 of the transposed X tile.
// ---------------------------------------------------------------------------
__global__ __launch_bounds__(256) void gemm_f32x2(
    const float* __restrict__ X,
    const float* __restrict__ W1,
    const float* __restrict__ b1,
    float* __restrict__ out)
{
    __shared__ float As[BK][ASW];    // [k][m] transposed X tile
    __shared__ float Bs[BK][BSW];    // [k][n] transposed W tile

    const int tid = threadIdx.x;
    const int ty  = tid >> 5;        // warp id 0..7 -> m sub-rows
    const int tx  = tid & 31;        // lane -> n columns
    const int m0  = blockIdx.x * ROWS;

    // ---- X loader: threads 0..191, row = tid>>2 (0..47), kseg = (tid&3)*4
    const int  xrow = tid >> 2;
    const int  xk   = (tid & 3) * 4;
    const bool xact = (tid < 192);
    int xgr = m0 + xrow;
    if (xgr > M_TOT - 1) xgr = M_TOT - 1;          // clamp (stores are masked)
    const float* xp = X + (size_t)xgr * NIN + xk;

    // ---- W loader: thread covers W row tid (0..255), 16 k = 4 float4
    const float* wp = W1 + (size_t)tid * NIN;

    // accumulators: acc[i2][j] lanes = outputs (m0+ty*6+2*i2 + {0,1}, tx*8+j)
    unsigned long long acc[3][8];
#pragma unroll
    for (int i = 0; i < 3; i++)
#pragma unroll
        for (int j = 0; j < 8; j++) acc[i][j] = pack2(0.0f, 0.0f);

    // ---- prologue: load chunk 0 into regs
    float4 xv = xact ? *reinterpret_cast<const float4*>(xp) : make_float4(0, 0, 0, 0);
    float4 wv0 = *reinterpret_cast<const float4*>(wp + 0);
    float4 wv1 = *reinterpret_cast<const float4*>(wp + 4);
    float4 wv2 = *reinterpret_cast<const float4*>(wp + 8);
    float4 wv3 = *reinterpret_cast<const float4*>(wp + 12);

    for (int c = 0; c < NCHUNK; c++) {
        // ---- stage current chunk regs -> smem (transposed)
        if (xact) {
            As[xk + 0][xrow] = xv.x;
            As[xk + 1][xrow] = xv.y;
            As[xk + 2][xrow] = xv.z;
            As[xk + 3][xrow] = xv.w;
        }
        Bs[ 0][tid] = wv0.x; Bs[ 1][tid] = wv0.y;
        Bs[ 2][tid] = wv0.z; Bs[ 3][tid] = wv0.w;
        Bs[ 4][tid] = wv1.x; Bs[ 5][tid] = wv1.y;
        Bs[ 6][tid] = wv1.z; Bs[ 7][tid] = wv1.w;
        Bs[ 8][tid] = wv2.x; Bs[ 9][tid] = wv2.y;
        Bs[10][tid] = wv2.z; Bs[11][tid] = wv2.w;
        Bs[12][tid] = wv3.x; Bs[13][tid] = wv3.y;
        Bs[14][tid] = wv3.z; Bs[15][tid] = wv3.w;
        __syncthreads();

        // ---- prefetch next chunk into regs (hidden under compute)
        if (c + 1 < NCHUNK) {
            const float* xq = xp + (size_t)(c + 1) * BK;
            const float* wq = wp + (size_t)(c + 1) * BK;
            if (xact) xv = *reinterpret_cast<const float4*>(xq);
            wv0 = *reinterpret_cast<const float4*>(wq + 0);
            wv1 = *reinterpret_cast<const float4*>(wq + 4);
            wv2 = *reinterpret_cast<const float4*>(wq + 8);
            wv3 = *reinterpret_cast<const float4*>(wq + 12);
        }

        // ---- compute: 16 k-slices, k ascending (order-preserving!)
#pragma unroll
        for (int k = 0; k < BK; k++) {
            // a pairs: LDS.64 of adjacent m-rows (warp-uniform address ->
            // broadcast through the crossbar)
            unsigned long long aa0 =
                *reinterpret_cast<const unsigned long long*>(&As[k][ty * 6 + 0]);
            unsigned long long aa1 =
                *reinterpret_cast<const unsigned long long*>(&As[k][ty * 6 + 2]);
            unsigned long long aa2 =
                *reinterpret_cast<const unsigned long long*>(&As[k][ty * 6 + 4]);
            // b: 8 scalars, broadcast-packed into both lanes
            float4 bv0 = *reinterpret_cast<const float4*>(&Bs[k][tx * 8 + 0]);
            float4 bv1 = *reinterpret_cast<const float4*>(&Bs[k][tx * 8 + 4]);
            unsigned long long bb[8];
            bb[0] = pack2(bv0.x, bv0.x); bb[1] = pack2(bv0.y, bv0.y);
            bb[2] = pack2(bv0.z, bv0.z); bb[3] = pack2(bv0.w, bv0.w);
            bb[4] = pack2(bv1.x, bv1.x); bb[5] = pack2(bv1.y, bv1.y);
            bb[6] = pack2(bv1.z, bv1.z); bb[7] = pack2(bv1.w, bv1.w);
#pragma unroll
            for (int j = 0; j < 8; j++) {
                fma_x2(acc[0][j], aa0, bb[j]);
                fma_x2(acc[1][j], aa1, bb[j]);
                fma_x2(acc[2][j], aa2, bb[j]);
            }
        }
        __syncthreads();
    }

    // ---- epilogue: single fp32 bias add (same as round 1), masked stores
#pragma unroll
    for (int j = 0; j < 8; j++) {
        const int col  = tx * 8 + j;
        const float bv = b1[col];
#pragma unroll
        for (int i = 0; i < 3; i++) {
            float lo, hi;
            unpack2(acc[i][j], lo, hi);
            const int row = m0 + ty * 6 + 2 * i;
            if (row < M_TOT)
                out[(size_t)row * NH + col] = lo + bv;
            if (row + 1 < M_TOT)
                out[(size_t)(row + 1) * NH + col] = hi + bv;
        }
    }
}

// ---------------------------------------------------------------------------
// VERBATIM round-1 fused scan (passed with rel_err = 0.0 on this cur1).
// ---------------------------------------------------------------------------
__global__ __launch_bounds__(256) void snn_scan(
    const float* __restrict__ cur1,
    const float* __restrict__ W2,
    const float* __restrict__ b2,
    float* __restrict__ out)
{
    const int b   = blockIdx.x;
    const int j   = threadIdx.x;
    const int wid = j >> 5;
    const int lid = j & 31;

    __shared__ float warp_sums[8][NO + 1];

    float w2c[NO];
#pragma unroll
    for (int o = 0; o < NO; o++) w2c[o] = W2[o * NH + j];

    float mem1 = 0.0f;
    float mem2 = 0.0f;
    const float bias2 = (j < NO) ? b2[j] : 0.0f;

    for (int t = 0; t < T_STEPS; t++) {
        const float c1 = cur1[((size_t)t * BATCH + b) * NH + j];
        mem1 = 0.9f * mem1 + c1;
        const float spk1 = (mem1 - 1.0f > 0.0f) ? 1.0f : 0.0f;
        mem1 -= spk1;

        float p[NO];
#pragma unroll
        for (int o = 0; o < NO; o++) p[o] = spk1 * w2c[o];

#pragma unroll
        for (int o = 0; o < NO; o++) {
#pragma unroll
            for (int off = 16; off > 0; off >>= 1)
                p[o] += __shfl_xor_sync(0xFFFFFFFFu, p[o], off);
        }
        if (lid == 0) {
#pragma unroll
            for (int o = 0; o < NO; o++) warp_sums[wid][o] = p[o];
        }
        __syncthreads();

        if (j < NO) {
            float c2 = bias2;
#pragma unroll
            for (int w = 0; w < 8; w++) c2 += warp_sums[w][j];
            mem2 = 0.9f * mem2 + c2;
            const float spk2 = (mem2 - 1.0f > 0.0f) ? 1.0f : 0.0f;
            mem2 -= spk2;
            out[((size_t)t * BATCH + b) * NO + j] = spk2;
        }
        __syncthreads();
    }
}

// ---------------------------------------------------------------------------
extern "C" void kernel_launch(void* const* d_in, const int* in_sizes, int n_in,
                              void* d_out, int out_size)
{
    const float* x  = (const float*)d_in[0];   // [50,128,128,128]
    const float* W1 = (const float*)d_in[1];   // [256,16384]
    const float* b1 = (const float*)d_in[2];   // [256]
    const float* W2 = (const float*)d_in[3];   // [11,256]
    const float* b2 = (const float*)d_in[4];   // [11]
    float* out = (float*)d_out;                // [50,128,11]

    float* cur1;
    cudaGetSymbolAddress((void**)&cur1, g_cur1);

    gemm_f32x2<<<NCTA, 256>>>(x, W1, b1, cur1);
    snn_scan<<<BATCH, NH>>>(cur1, W2, b2, out);
}